// round 1
// baseline (speedup 1.0000x reference)
#include <cuda_runtime.h>

// Yolo_Loss: S=56, B=5, C=20, N=128.
// predicts: [N,S,S,B,25] f32, targets: [N,S,S,25] f32, anchors: [5,2] f32.
// Output: scalar f32 loss.

#define S_DIM 56
#define N_IMG 128
#define B_BOX 5
#define C_CLS 20
#define CVEC  25                       // C+5
#define CELLS (N_IMG * S_DIM * S_DIM)  // 401408
#define CPB   128                      // cells per block (== threads per block)
#define PW    (CPB * CVEC * B_BOX)     // 16000 floats of predicts per block
#define TW    (CPB * CVEC)             // 3200 floats of targets per block
#define SMEM_BYTES ((PW + TW) * 4)     // 76800 B dynamic smem

__global__ void yolo_zero_out(float* o) { *o = 0.0f; }

__device__ __forceinline__ float sigmoid_f(float x) {
    // sigmoid(x) = 0.5 * tanh(0.5x) + 0.5  (1 MUFU instead of EX2+RCP)
    float t;
    asm("tanh.approx.f32 %0, %1;" : "=f"(t) : "f"(x * 0.5f));
    return fmaf(0.5f, t, 0.5f);
}

__global__ __launch_bounds__(CPB) void yolo_loss_kernel(
    const float* __restrict__ gp,   // predicts
    const float* __restrict__ gt,   // targets
    const float* __restrict__ ga,   // anchors (10 floats)
    float* __restrict__ out)
{
    extern __shared__ float sm[];
    float* sp = sm;        // [PW] predicts for this block's cells
    float* st = sm + PW;   // [TW] targets  for this block's cells

    const int tid = threadIdx.x;

    // ---- Coalesced staging: global -> shared via float4 ----
    // block offset in bytes: blockIdx * 64000 (p) / 12800 (t): both 16B-aligned.
    const float4* p4 = (const float4*)(gp + (size_t)blockIdx.x * PW);
    const float4* t4 = (const float4*)(gt + (size_t)blockIdx.x * TW);
    float4* sp4 = (float4*)sp;
    float4* st4 = (float4*)st;

#pragma unroll 4
    for (int i = tid; i < PW / 4; i += CPB) sp4[i] = p4[i];   // 31.25 iters
#pragma unroll 2
    for (int i = tid; i < TW / 4; i += CPB) st4[i] = t4[i];   // 6.25 iters
    __syncthreads();

    // ---- Per-cell compute. smem strides 125 / 25 words: odd -> bank-conflict-free ----
    const float* pc = sp + tid * (CVEC * B_BOX);
    const float* tc = st + tid * CVEC;

    const float e   = tc[C_CLS];
    const float tcx = tc[C_CLS + 1], tcy = tc[C_CLS + 2];
    const float tw  = tc[C_CLS + 3], th  = tc[C_CLS + 4];
    const float tx1 = tcx - 0.5f * tw, ty1 = tcy - 0.5f * th;
    const float tx2 = tcx + 0.5f * tw, ty2 = tcy + 0.5f * th;
    const float area_t = tw * th;

    // Argmax over IoU via cross-multiplication (dens > 0); init guarantees b=0 wins first.
    float bnum = -1.0f, bden = 1.0f;
    int   bidx = 0;
    float bsx = 0.f, bsy = 0.f, bw = 0.f, bh = 0.f;

#pragma unroll
    for (int b = 0; b < B_BOX; ++b) {
        const float* pb = pc + b * CVEC;
        const float sx = sigmoid_f(pb[C_CLS + 1]);
        const float sy = sigmoid_f(pb[C_CLS + 2]);
        const float w  = __expf(pb[C_CLS + 3]) * __ldg(ga + 2 * b);
        const float h  = __expf(pb[C_CLS + 4]) * __ldg(ga + 2 * b + 1);

        const float x1 = sx - 0.5f * w, y1 = sy - 0.5f * h;
        const float x2 = sx + 0.5f * w, y2 = sy + 0.5f * h;
        const float lx = fmaxf(x1, tx1), ly = fmaxf(y1, ty1);
        const float rx = fminf(x2, tx2), ry = fminf(y2, ty2);
        const float wi = fmaxf(rx - lx, 0.0f);
        const float hi = fmaxf(ry - ly, 0.0f);
        const float inter = wi * hi;
        const float den   = fmaf(w, h, area_t) - inter;  // area_p + area_t - inter

        // iou_b > iou_best  <=>  inter*bden > bnum*den   (strict > == first-max argmax)
        if (inter * bden > bnum * den) {
            bidx = b; bnum = inter; bden = den;
            bsx = sx; bsy = sy; bw = w; bh = h;
        }
    }

    const float e2 = e * e;

    // loss_xcyc
    const float dx = bsx - tcx, dy = bsy - tcy;
    float loss = e2 * (dx * dx + dy * dy);

    // loss_wh: sign(w)*sqrt(|w|+1e-6)  (w >= 0 in practice; handle sign(0)=0)
    const float pw = (bw > 0.f) ? sqrtf(bw + 1e-6f)
                                : ((bw < 0.f) ? -sqrtf(-bw + 1e-6f) : 0.f);
    const float ph = (bh > 0.f) ? sqrtf(bh + 1e-6f)
                                : ((bh < 0.f) ? -sqrtf(-bh + 1e-6f) : 0.f);
    const float dw = pw - tw, dh = ph - th;
    loss += e2 * (dw * dw + dh * dh);

    // loss_cls (class 0 of best box scaled by best_idx)
    const float* pbest = pc + bidx * CVEC;
    const float fbidx = (float)bidx;
    float cls = 0.0f;
#pragma unroll
    for (int c = 0; c < C_CLS; ++c) {
        float pv = pbest[c];
        if (c == 0) pv *= fbidx;
        const float d = pv - tc[c];
        cls = fmaf(d, d, cls);
    }
    loss += e2 * cls;

    // loss_obj + loss_noobj: [e^2 + (1-e)^2] * (pobj - e)^2
    const float dobj   = pbest[C_CLS] - e;
    const float one_me = 1.0f - e;
    loss += (e2 + one_me * one_me) * dobj * dobj;

    // ---- Reduction: warp shuffle -> block -> global atomic ----
#pragma unroll
    for (int o = 16; o; o >>= 1)
        loss += __shfl_xor_sync(0xffffffffu, loss, o);

    __shared__ float wsum[CPB / 32];
    if ((tid & 31) == 0) wsum[tid >> 5] = loss;
    __syncthreads();
    if (tid == 0) {
        float s = 0.0f;
#pragma unroll
        for (int i = 0; i < CPB / 32; ++i) s += wsum[i];
        atomicAdd(out, s);
    }
}

extern "C" void kernel_launch(void* const* d_in, const int* in_sizes, int n_in,
                              void* d_out, int out_size)
{
    const float* p = (const float*)d_in[0];
    const float* t = (const float*)d_in[1];
    const float* a = (const float*)d_in[2];
    float* out = (float*)d_out;

    cudaFuncSetAttribute(yolo_loss_kernel,
                         cudaFuncAttributeMaxDynamicSharedMemorySize, SMEM_BYTES);

    yolo_zero_out<<<1, 1>>>(out);
    yolo_loss_kernel<<<CELLS / CPB, CPB, SMEM_BYTES>>>(p, t, a, out);
}

// round 2
// speedup vs baseline: 2.3812x; 2.3812x over previous
#include <cuda_runtime.h>
#include <cstdint>

// Yolo_Loss: S=56, B=5, C=20, N=128.
// predicts: [N,S,S,B,25] f32, targets: [N,S,S,25] f32, anchors: [5,2] f32.
// Output: scalar f32 loss.

#define S_DIM 56
#define N_IMG 128
#define B_BOX 5
#define C_CLS 20
#define CVEC  25                       // C+5
#define CELLS (N_IMG * S_DIM * S_DIM)  // 401408
#define CPB   128                      // cells per block (== threads per block)
#define PW    (CPB * CVEC * B_BOX)     // 16000 floats of predicts per block
#define TW    (CPB * CVEC)             // 3200 floats of targets per block
#define PBYTES (PW * 4)                // 64000 B  (16B-multiple)
#define TBYTES (TW * 4)                // 12800 B  (16B-multiple)
#define SMEM_BYTES (PBYTES + TBYTES)   // 76800 B dynamic smem

__global__ void yolo_zero_out(float* o) { *o = 0.0f; }

__device__ __forceinline__ float sigmoid_f(float x) {
    // sigmoid(x) = 0.5 * tanh(0.5x) + 0.5  (1 MUFU)
    float t;
    asm("tanh.approx.f32 %0, %1;" : "=f"(t) : "f"(x * 0.5f));
    return fmaf(0.5f, t, 0.5f);
}

__device__ __forceinline__ uint32_t smem_u32(const void* p) {
    return (uint32_t)__cvta_generic_to_shared(p);
}

__global__ __launch_bounds__(CPB) void yolo_loss_kernel(
    const float* __restrict__ gp,   // predicts
    const float* __restrict__ gt,   // targets
    const float* __restrict__ ga,   // anchors (10 floats)
    float* __restrict__ out)
{
    extern __shared__ __align__(128) float sm[];
    float* sp = sm;        // [PW] predicts for this block's cells
    float* st = sm + PW;   // [TW] targets  for this block's cells
    __shared__ __align__(8) unsigned long long mbar;

    const int tid = threadIdx.x;
    const uint32_t mbar_a = smem_u32(&mbar);

    if (tid == 0) {
        asm volatile("mbarrier.init.shared.b64 [%0], 1;" :: "r"(mbar_a) : "memory");
    }
    __syncthreads();

    // ---- One-shot TMA bulk copy of the whole tile (max MLP, zero reg pressure) ----
    if (tid == 0) {
        asm volatile("mbarrier.arrive.expect_tx.shared.b64 _, [%0], %1;"
                     :: "r"(mbar_a), "r"((uint32_t)SMEM_BYTES) : "memory");
        const char* gpp = (const char*)(gp + (size_t)blockIdx.x * PW);
        const char* gtp = (const char*)(gt + (size_t)blockIdx.x * TW);
        asm volatile(
            "cp.async.bulk.shared::cta.global.mbarrier::complete_tx::bytes [%0], [%1], %2, [%3];"
            :: "r"(smem_u32(sp)), "l"(gpp), "r"((uint32_t)PBYTES), "r"(mbar_a) : "memory");
        asm volatile(
            "cp.async.bulk.shared::cta.global.mbarrier::complete_tx::bytes [%0], [%1], %2, [%3];"
            :: "r"(smem_u32(st)), "l"(gtp), "r"((uint32_t)TBYTES), "r"(mbar_a) : "memory");
    }

    // ---- Wait for the bulk copy (acquire orders subsequent ld.shared) ----
    {
        uint32_t done;
        asm volatile(
            "{\n\t.reg .pred p;\n\t"
            "mbarrier.try_wait.parity.acquire.cta.shared::cta.b64 p, [%1], 0;\n\t"
            "selp.b32 %0, 1, 0, p;\n\t}"
            : "=r"(done) : "r"(mbar_a) : "memory");
        if (!done) {
            asm volatile(
                "{\n\t.reg .pred P1;\n\t"
                "WAIT_LOOP_%=:\n\t"
                "mbarrier.try_wait.parity.acquire.cta.shared::cta.b64 P1, [%0], 0, 0x989680;\n\t"
                "@P1 bra.uni WAIT_DONE_%=;\n\t"
                "bra.uni WAIT_LOOP_%=;\n\t"
                "WAIT_DONE_%=:\n\t}"
                :: "r"(mbar_a) : "memory");
        }
    }

    // ---- Per-cell compute. smem strides 125 / 25 words: odd -> bank-conflict-free ----
    const float* pc = sp + tid * (CVEC * B_BOX);
    const float* tc = st + tid * CVEC;

    const float e   = tc[C_CLS];
    const float tcx = tc[C_CLS + 1], tcy = tc[C_CLS + 2];
    const float tw  = tc[C_CLS + 3], th  = tc[C_CLS + 4];
    const float tx1 = tcx - 0.5f * tw, ty1 = tcy - 0.5f * th;
    const float tx2 = tcx + 0.5f * tw, ty2 = tcy + 0.5f * th;
    const float area_t = tw * th;

    // Argmax over IoU via cross-multiplication (dens > 0); init guarantees b=0 wins first.
    float bnum = -1.0f, bden = 1.0f;
    int   bidx = 0;
    float bsx = 0.f, bsy = 0.f, bw = 0.f, bh = 0.f;

#pragma unroll
    for (int b = 0; b < B_BOX; ++b) {
        const float* pb = pc + b * CVEC;
        const float sx = sigmoid_f(pb[C_CLS + 1]);
        const float sy = sigmoid_f(pb[C_CLS + 2]);
        const float w  = __expf(pb[C_CLS + 3]) * __ldg(ga + 2 * b);
        const float h  = __expf(pb[C_CLS + 4]) * __ldg(ga + 2 * b + 1);

        const float x1 = sx - 0.5f * w, y1 = sy - 0.5f * h;
        const float x2 = sx + 0.5f * w, y2 = sy + 0.5f * h;
        const float lx = fmaxf(x1, tx1), ly = fmaxf(y1, ty1);
        const float rx = fminf(x2, tx2), ry = fminf(y2, ty2);
        const float wi = fmaxf(rx - lx, 0.0f);
        const float hi = fmaxf(ry - ly, 0.0f);
        const float inter = wi * hi;
        const float den   = fmaf(w, h, area_t) - inter;  // area_p + area_t - inter

        // iou_b > iou_best  <=>  inter*bden > bnum*den   (strict > == first-max argmax)
        if (inter * bden > bnum * den) {
            bidx = b; bnum = inter; bden = den;
            bsx = sx; bsy = sy; bw = w; bh = h;
        }
    }

    const float e2 = e * e;

    // loss_xcyc
    const float dx = bsx - tcx, dy = bsy - tcy;
    float loss = e2 * (dx * dx + dy * dy);

    // loss_wh: sign(w)*sqrt(|w|+1e-6)
    const float pw = (bw > 0.f) ? sqrtf(bw + 1e-6f)
                                : ((bw < 0.f) ? -sqrtf(-bw + 1e-6f) : 0.f);
    const float ph = (bh > 0.f) ? sqrtf(bh + 1e-6f)
                                : ((bh < 0.f) ? -sqrtf(-bh + 1e-6f) : 0.f);
    const float dw = pw - tw, dh = ph - th;
    loss += e2 * (dw * dw + dh * dh);

    // loss_cls (class 0 of best box scaled by best_idx)
    const float* pbest = pc + bidx * CVEC;
    const float fbidx = (float)bidx;
    float cls = 0.0f;
#pragma unroll
    for (int c = 0; c < C_CLS; ++c) {
        float pv = pbest[c];
        if (c == 0) pv *= fbidx;
        const float d = pv - tc[c];
        cls = fmaf(d, d, cls);
    }
    loss += e2 * cls;

    // loss_obj + loss_noobj: [e^2 + (1-e)^2] * (pobj - e)^2
    const float dobj   = pbest[C_CLS] - e;
    const float one_me = 1.0f - e;
    loss += (e2 + one_me * one_me) * dobj * dobj;

    // ---- Reduction: warp shuffle -> block -> global atomic ----
#pragma unroll
    for (int o = 16; o; o >>= 1)
        loss += __shfl_xor_sync(0xffffffffu, loss, o);

    __shared__ float wsum[CPB / 32];
    if ((tid & 31) == 0) wsum[tid >> 5] = loss;
    __syncthreads();
    if (tid == 0) {
        float s = 0.0f;
#pragma unroll
        for (int i = 0; i < CPB / 32; ++i) s += wsum[i];
        atomicAdd(out, s);
    }
}

extern "C" void kernel_launch(void* const* d_in, const int* in_sizes, int n_in,
                              void* d_out, int out_size)
{
    const float* p = (const float*)d_in[0];
    const float* t = (const float*)d_in[1];
    const float* a = (const float*)d_in[2];
    float* out = (float*)d_out;

    cudaFuncSetAttribute(yolo_loss_kernel,
                         cudaFuncAttributeMaxDynamicSharedMemorySize, SMEM_BYTES);

    yolo_zero_out<<<1, 1>>>(out);
    yolo_loss_kernel<<<CELLS / CPB, CPB, SMEM_BYTES>>>(p, t, a, out);
}

// round 3
// speedup vs baseline: 2.4072x; 1.0109x over previous
#include <cuda_runtime.h>
#include <cstdint>

// Yolo_Loss: S=56, B=5, C=20, N=128.
// predicts: [N,S,S,B,25] f32, targets: [N,S,S,25] f32, anchors: [5,2] f32.
// Output: scalar f32 loss.
// Persistent grid (148 CTAs = 1 wave), double-buffered TMA bulk copies,
// last-CTA-out completion (no separate zeroing kernel).

#define S_DIM 56
#define N_IMG 128
#define B_BOX 5
#define C_CLS 20
#define CVEC  25
#define CELLS (N_IMG * S_DIM * S_DIM)   // 401408
#define TILE_CELLS 128
#define THREADS    128
#define NTILES (CELLS / TILE_CELLS)     // 3136
#define GRID   148                      // 1 CTA per SM, single wave

#define TILE_P (TILE_CELLS * CVEC * B_BOX)  // 16000 floats
#define TILE_T (TILE_CELLS * CVEC)          //  3200 floats
#define TILE_F (TILE_P + TILE_T)            // 19200 floats per buffer
#define TPB    (TILE_P * 4)                 // 64000 B
#define TTB    (TILE_T * 4)                 // 12800 B
#define TILE_BYTES (TPB + TTB)              // 76800 B
#define SMEM_BYTES (2 * TILE_BYTES)         // 153600 B dynamic smem

__device__ float        g_sum  = 0.0f;
__device__ unsigned int g_done = 0u;

__device__ __forceinline__ float sigmoid_f(float x) {
    float t;
    asm("tanh.approx.f32 %0, %1;" : "=f"(t) : "f"(x * 0.5f));
    return fmaf(0.5f, t, 0.5f);
}

__device__ __forceinline__ uint32_t smem_u32(const void* p) {
    return (uint32_t)__cvta_generic_to_shared(p);
}

__device__ __forceinline__ void mbar_wait(uint32_t mbar_a, int parity) {
    uint32_t done;
    asm volatile(
        "{\n\t.reg .pred p;\n\t"
        "mbarrier.try_wait.parity.acquire.cta.shared::cta.b64 p, [%1], %2;\n\t"
        "selp.b32 %0, 1, 0, p;\n\t}"
        : "=r"(done) : "r"(mbar_a), "r"((uint32_t)parity) : "memory");
    if (!done) {
        asm volatile(
            "{\n\t.reg .pred P1;\n\t"
            "WAIT_LOOP_%=:\n\t"
            "mbarrier.try_wait.parity.acquire.cta.shared::cta.b64 P1, [%0], %1, 0x989680;\n\t"
            "@P1 bra.uni WAIT_DONE_%=;\n\t"
            "bra.uni WAIT_LOOP_%=;\n\t"
            "WAIT_DONE_%=:\n\t}"
            :: "r"(mbar_a), "r"((uint32_t)parity) : "memory");
    }
}

__global__ __launch_bounds__(THREADS) void yolo_loss_kernel(
    const float* __restrict__ gp,
    const float* __restrict__ gt,
    const float* __restrict__ ga,
    float* __restrict__ out)
{
    extern __shared__ __align__(128) float sm[];          // 2 buffers of TILE_F floats
    __shared__ __align__(8) unsigned long long mbar[2];
    __shared__ float wsum[THREADS / 32];

    const int tid = threadIdx.x;
    const int bid = blockIdx.x;
    const uint32_t mb0 = smem_u32(&mbar[0]);
    const uint32_t mb1 = smem_u32(&mbar[1]);

    if (tid == 0) {
        asm volatile("mbarrier.init.shared.b64 [%0], 1;" :: "r"(mb0) : "memory");
        asm volatile("mbarrier.init.shared.b64 [%0], 1;" :: "r"(mb1) : "memory");
    }
    __syncthreads();

    const int nt = (NTILES - bid + GRID - 1) / GRID;      // tiles for this CTA (21 or 22)

    // ---- TMA issue helper (tid 0 only): tile (bid + k*GRID) -> buffer (k&1) ----
    auto issue = [&](int k) {
        const int t = bid + k * GRID;
        const int b = k & 1;
        const uint32_t mba = b ? mb1 : mb0;
        asm volatile("mbarrier.arrive.expect_tx.shared.b64 _, [%0], %1;"
                     :: "r"(mba), "r"((uint32_t)TILE_BYTES) : "memory");
        const char* srcp = (const char*)(gp + (size_t)t * TILE_P);
        const char* srct = (const char*)(gt + (size_t)t * TILE_T);
        const uint32_t dst = smem_u32(sm + b * TILE_F);
        asm volatile(
            "cp.async.bulk.shared::cta.global.mbarrier::complete_tx::bytes [%0], [%1], %2, [%3];"
            :: "r"(dst), "l"(srcp), "r"((uint32_t)TPB), "r"(mba) : "memory");
        asm volatile(
            "cp.async.bulk.shared::cta.global.mbarrier::complete_tx::bytes [%0], [%1], %2, [%3];"
            :: "r"(dst + TPB), "l"(srct), "r"((uint32_t)TTB), "r"(mba) : "memory");
    };

    if (tid == 0) {
        issue(0);
        if (nt > 1) issue(1);
    }

    // anchors: tiny, read once into registers
    float anc[2 * B_BOX];
#pragma unroll
    for (int i = 0; i < 2 * B_BOX; ++i) anc[i] = __ldg(ga + i);

    float loss = 0.0f;
    int ph0 = 0, ph1 = 0;

    for (int k = 0; k < nt; ++k) {
        const int b = k & 1;
        if (b) { mbar_wait(mb1, ph1); ph1 ^= 1; }
        else   { mbar_wait(mb0, ph0); ph0 ^= 1; }

        const float* sp = sm + b * TILE_F;
        const float* st = sp + TILE_P;
        const float* pc = sp + tid * (CVEC * B_BOX);
        const float* tc = st + tid * CVEC;

        const float e   = tc[C_CLS];
        const float tcx = tc[C_CLS + 1], tcy = tc[C_CLS + 2];
        const float tw  = tc[C_CLS + 3], th  = tc[C_CLS + 4];
        const float tx1 = tcx - 0.5f * tw, ty1 = tcy - 0.5f * th;
        const float tx2 = tcx + 0.5f * tw, ty2 = tcy + 0.5f * th;
        const float area_t = tw * th;

        float bnum = -1.0f, bden = 1.0f;
        int   bidx = 0;
        float bsx = 0.f, bsy = 0.f, bw = 0.f, bh = 0.f;

#pragma unroll
        for (int bb = 0; bb < B_BOX; ++bb) {
            const float* pb = pc + bb * CVEC;
            const float sx = sigmoid_f(pb[C_CLS + 1]);
            const float sy = sigmoid_f(pb[C_CLS + 2]);
            const float w  = __expf(pb[C_CLS + 3]) * anc[2 * bb];
            const float h  = __expf(pb[C_CLS + 4]) * anc[2 * bb + 1];

            const float x1 = sx - 0.5f * w, y1 = sy - 0.5f * h;
            const float x2 = sx + 0.5f * w, y2 = sy + 0.5f * h;
            const float lx = fmaxf(x1, tx1), ly = fmaxf(y1, ty1);
            const float rx = fminf(x2, tx2), ry = fminf(y2, ty2);
            const float wi = fmaxf(rx - lx, 0.0f);
            const float hi = fmaxf(ry - ly, 0.0f);
            const float inter = wi * hi;
            const float den   = fmaf(w, h, area_t) - inter;

            if (inter * bden > bnum * den) {   // strict > == first-max argmax
                bidx = bb; bnum = inter; bden = den;
                bsx = sx; bsy = sy; bw = w; bh = h;
            }
        }

        const float e2 = e * e;

        const float dx = bsx - tcx, dy = bsy - tcy;
        float l = e2 * (dx * dx + dy * dy);

        const float pw = (bw > 0.f) ? sqrtf(bw + 1e-6f)
                                    : ((bw < 0.f) ? -sqrtf(-bw + 1e-6f) : 0.f);
        const float ph = (bh > 0.f) ? sqrtf(bh + 1e-6f)
                                    : ((bh < 0.f) ? -sqrtf(-bh + 1e-6f) : 0.f);
        const float dw = pw - tw, dh = ph - th;
        l += e2 * (dw * dw + dh * dh);

        const float* pbest = pc + bidx * CVEC;
        const float fbidx = (float)bidx;
        float cls = 0.0f;
#pragma unroll
        for (int c = 0; c < C_CLS; ++c) {
            float pv = pbest[c];
            if (c == 0) pv *= fbidx;
            const float d = pv - tc[c];
            cls = fmaf(d, d, cls);
        }
        l += e2 * cls;

        const float dobj   = pbest[C_CLS] - e;
        const float one_me = 1.0f - e;
        l += (e2 + one_me * one_me) * dobj * dobj;

        loss += l;

        __syncthreads();                      // all readers done with buffer b
        if (tid == 0 && k + 2 < nt) issue(k + 2);
    }

    // ---- CTA reduction ----
#pragma unroll
    for (int o = 16; o; o >>= 1)
        loss += __shfl_xor_sync(0xffffffffu, loss, o);
    if ((tid & 31) == 0) wsum[tid >> 5] = loss;
    __syncthreads();

    // ---- Grid completion: last CTA writes out and resets globals ----
    if (tid == 0) {
        float s = 0.0f;
#pragma unroll
        for (int i = 0; i < THREADS / 32; ++i) s += wsum[i];
        atomicAdd(&g_sum, s);
        __threadfence();
        const unsigned r = atomicAdd(&g_done, 1u);
        if (r == GRID - 1) {
            const float tot = *((volatile float*)&g_sum);
            *out = tot;
            *((volatile float*)&g_sum) = 0.0f;          // restore for next replay
            *((volatile unsigned*)&g_done) = 0u;
            __threadfence();
        }
    }
}

extern "C" void kernel_launch(void* const* d_in, const int* in_sizes, int n_in,
                              void* d_out, int out_size)
{
    const float* p = (const float*)d_in[0];
    const float* t = (const float*)d_in[1];
    const float* a = (const float*)d_in[2];
    float* out = (float*)d_out;

    cudaFuncSetAttribute(yolo_loss_kernel,
                         cudaFuncAttributeMaxDynamicSharedMemorySize, SMEM_BYTES);

    yolo_loss_kernel<<<GRID, THREADS, SMEM_BYTES>>>(p, t, a, out);
}